// round 13
// baseline (speedup 1.0000x reference)
#include <cuda_runtime.h>
#include <cuda_bf16.h>
#include <math.h>
#include <stdint.h>

// Problem-instance constants (VectorQuantizerEnt: B=32,T=512,D=512,K=2048)
#define KC   2048
#define DD   512
#define NMAX 16384
#define EPSQ 1e-8f
#define MARGIN 0.02f
#define MAXCAND 16
// sum_k p*log2((p+eps)/p) ~= K*eps*log2(e)  (exact to ~3e-10 here since eps/p <= 1e-4)
#define EPS_CORR 2.9546194437325826e-5f

// ---------------- scratch (static device globals) ---------------------------
__device__ __nv_bfloat16 g_simh[(size_t)NMAX * KC];   // similarities, bf16 (67MB)
__device__ __nv_bfloat16 g_Ah[(size_t)NMAX * DD];
__device__ __nv_bfloat16 g_Bh[(size_t)KC * DD];
__device__ float  g_div[KC];
__device__ float  g_cnt[KC];
__device__ int    g_idx[NMAX];
__device__ int    g_cand[NMAX][MAXCAND];
__device__ int    g_ncand[NMAX];
__device__ double g_hsum;

// ---------------- small PTX helpers -----------------------------------------
static __device__ __forceinline__ uint32_t smem_u32(const void* p) {
    uint32_t a;
    asm("{ .reg .u64 t; cvta.to.shared.u64 t, %1; cvt.u32.u64 %0, t; }" : "=r"(a) : "l"(p));
    return a;
}
static __device__ __forceinline__ void ldsm_x4(uint32_t* r, uint32_t addr) {
    asm volatile("ldmatrix.sync.aligned.m8n8.x4.shared.b16 {%0,%1,%2,%3}, [%4];"
                 : "=r"(r[0]), "=r"(r[1]), "=r"(r[2]), "=r"(r[3]) : "r"(addr));
}
static __device__ __forceinline__ void mma16816(float* c, const uint32_t* a, const uint32_t* b) {
    asm volatile("mma.sync.aligned.m16n8k16.row.col.f32.bf16.bf16.f32 "
                 "{%0,%1,%2,%3}, {%4,%5,%6,%7}, {%8,%9}, {%0,%1,%2,%3};"
                 : "+f"(c[0]), "+f"(c[1]), "+f"(c[2]), "+f"(c[3])
                 : "r"(a[0]), "r"(a[1]), "r"(a[2]), "r"(a[3]), "r"(b[0]), "r"(b[1]));
}

// ---------------- reductions ------------------------------------------------
__device__ __forceinline__ float blockSum(float v) {
    __shared__ float s[8];
    int t = threadIdx.x, w = t >> 5, l = t & 31;
#pragma unroll
    for (int o = 16; o; o >>= 1) v += __shfl_xor_sync(0xffffffffu, v, o);
    if (l == 0) s[w] = v;
    __syncthreads();
    if (w == 0) {
        float x = (l < 8) ? s[l] : 0.0f;
#pragma unroll
        for (int o = 4; o; o >>= 1) x += __shfl_xor_sync(0xffffffffu, x, o);
        if (l == 0) s[0] = x;
    }
    __syncthreads();
    float r = s[0];
    __syncthreads();
    return r;
}

// block max of two values simultaneously
__device__ __forceinline__ float2 blockMax2(float a, float b) {
    __shared__ float2 s2[8];
    int t = threadIdx.x, w = t >> 5, l = t & 31;
#pragma unroll
    for (int o = 16; o; o >>= 1) {
        a = fmaxf(a, __shfl_xor_sync(0xffffffffu, a, o));
        b = fmaxf(b, __shfl_xor_sync(0xffffffffu, b, o));
    }
    if (l == 0) s2[w] = make_float2(a, b);
    __syncthreads();
    if (w == 0) {
        float x = (l < 8) ? s2[l].x : -3.4e38f;
        float y = (l < 8) ? s2[l].y : -3.4e38f;
#pragma unroll
        for (int o = 4; o; o >>= 1) {
            x = fmaxf(x, __shfl_xor_sync(0xffffffffu, x, o));
            y = fmaxf(y, __shfl_xor_sync(0xffffffffu, y, o));
        }
        if (l == 0) s2[0] = make_float2(x, y);
    }
    __syncthreads();
    float2 r = s2[0];
    __syncthreads();
    return r;
}

// block sum of four values simultaneously
__device__ __forceinline__ float4 blockSum4(float a, float b, float c, float d) {
    __shared__ float4 s4[8];
    int t = threadIdx.x, w = t >> 5, l = t & 31;
#pragma unroll
    for (int o = 16; o; o >>= 1) {
        a += __shfl_xor_sync(0xffffffffu, a, o);
        b += __shfl_xor_sync(0xffffffffu, b, o);
        c += __shfl_xor_sync(0xffffffffu, c, o);
        d += __shfl_xor_sync(0xffffffffu, d, o);
    }
    if (l == 0) s4[w] = make_float4(a, b, c, d);
    __syncthreads();
    if (w == 0) {
        float4 v = (l < 8) ? s4[l] : make_float4(0.f, 0.f, 0.f, 0.f);
#pragma unroll
        for (int o = 4; o; o >>= 1) {
            v.x += __shfl_xor_sync(0xffffffffu, v.x, o);
            v.y += __shfl_xor_sync(0xffffffffu, v.y, o);
            v.z += __shfl_xor_sync(0xffffffffu, v.z, o);
            v.w += __shfl_xor_sync(0xffffffffu, v.w, o);
        }
        if (l == 0) s4[0] = v;
    }
    __syncthreads();
    float4 r = s4[0];
    __syncthreads();
    return r;
}

// ---------------- kernels ---------------------------------------------------
// fp32 -> bf16 convert of inputs + codebook; also zero-init accumulators
__global__ void convert_kernel(const float4* __restrict__ A, const float4* __restrict__ B) {
    const int NA4 = NMAX * DD / 4;
    const int NB4 = KC * DD / 4;
    int i = blockIdx.x * 256 + threadIdx.x;
    if (i < KC) { g_div[i] = 0.0f; g_cnt[i] = 0.0f; }
    if (i == 0) g_hsum = 0.0;
    const float4* src;
    __nv_bfloat162* oh;
    int j;
    if (i < NA4) {
        src = A; j = i; oh = (__nv_bfloat162*)g_Ah;
    } else if (i < NA4 + NB4) {
        src = B; j = i - NA4; oh = (__nv_bfloat162*)g_Bh;
    } else return;
    float4 f = src[j];
    oh[2 * j]     = __floats2bfloat162_rn(f.x, f.y);
    oh[2 * j + 1] = __floats2bfloat162_rn(f.z, f.w);
}

// ---- GEMM: C = A_bf16 * B_bf16^T, 128x256 tile, BK=64, 3-stage cp.async ----
#define BMM 128
#define BNN 256
#define MM_STAGE 49152u   // 16KB A + 32KB B

// load one stage: A 128x64 (16KB) + B 256x64 (32KB), SW128 rows of 128B
static __device__ __forceinline__ void load_chunk(
    uint32_t s,
    const __nv_bfloat16* __restrict__ Ah, const __nv_bfloat16* __restrict__ Bh,
    int k0, int t)
{
    const char* pA = (const char*)(Ah + k0);
    const char* pB = (const char*)(Bh + k0);
#pragma unroll
    for (int i = 0; i < 2; i++) {                 // A: 1024 16B units / 512 thr
        int u = t + i * 512;
        int row = u >> 3, c16 = u & 7;
        uint32_t off = (uint32_t)row * 128u + (uint32_t)c16 * 16u;
        uint32_t sw  = off ^ ((off >> 3) & 0x70);
        const char* src = pA + (size_t)row * (DD * 2) + c16 * 16;
        asm volatile("cp.async.cg.shared.global [%0], [%1], 16;" :: "r"(s + sw), "l"(src));
    }
#pragma unroll
    for (int i = 0; i < 4; i++) {                 // B: 2048 16B units / 512 thr
        int u = t + i * 512;
        int row = u >> 3, c16 = u & 7;
        uint32_t off = (uint32_t)row * 128u + (uint32_t)c16 * 16u;
        uint32_t sw  = off ^ ((off >> 3) & 0x70);
        const char* src = pB + (size_t)row * (DD * 2) + c16 * 16;
        asm volatile("cp.async.cg.shared.global [%0], [%1], 16;" :: "r"(s + 16384u + sw), "l"(src));
    }
}

// 16 warps (4m x 4n), warp tile 32x64; epilogue writes bf16 sims
__global__ __launch_bounds__(512, 1) void mm_kernel() {
    extern __shared__ char dyn[];
    uint32_t raw  = smem_u32(dyn);
    uint32_t base = (raw + 1023u) & ~1023u;
    int t = threadIdx.x, wid = t >> 5, lane = t & 31;
    int bc = blockIdx.x * BNN, br = blockIdx.y * BMM;
    int wm = (wid & 3) * 32;      // warp m offset
    int wn = (wid >> 2) * 64;     // warp n offset

    const __nv_bfloat16* Ah = g_Ah + (size_t)br * DD;
    const __nv_bfloat16* Bh = g_Bh + (size_t)bc * DD;

    float acc[2][8][4];
#pragma unroll
    for (int i = 0; i < 2; i++)
#pragma unroll
        for (int j = 0; j < 8; j++)
#pragma unroll
            for (int q = 0; q < 4; q++) acc[i][j][q] = 0.0f;

    const int a_row  = lane & 15;
    const int a_koff = (lane >> 4) * 16;
    const int b_nrow = (lane & 7) + ((lane >> 4) * 8);
    const int b_koff = ((lane >> 3) & 1) * 16;

    load_chunk(base,            Ah, Bh, 0,  t);
    asm volatile("cp.async.commit_group;");
    load_chunk(base + MM_STAGE, Ah, Bh, 64, t);
    asm volatile("cp.async.commit_group;");

    for (int c = 0; c < 8; c++) {
        uint32_t s = base + (uint32_t)(c % 3) * MM_STAGE;
        if (c < 6) {
            uint32_t ns = base + (uint32_t)((c + 2) % 3) * MM_STAGE;
            load_chunk(ns, Ah, Bh, (c + 2) * 64, t);
            asm volatile("cp.async.commit_group;");
            asm volatile("cp.async.wait_group 2;");
        } else if (c == 6) {
            asm volatile("cp.async.wait_group 1;");
        } else {
            asm volatile("cp.async.wait_group 0;");
        }
        __syncthreads();

#pragma unroll
        for (int ks = 0; ks < 4; ks++) {
            uint32_t ah[2][4], bh[4][4];
#pragma unroll
            for (int mt = 0; mt < 2; mt++) {
                uint32_t off = (uint32_t)(wm + mt * 16 + a_row) * 128u
                             + (uint32_t)ks * 32u + (uint32_t)a_koff;
                ldsm_x4(ah[mt], s + (off ^ ((off >> 3) & 0x70)));
            }
#pragma unroll
            for (int nt = 0; nt < 4; nt++) {
                uint32_t off = (uint32_t)(wn + nt * 16 + b_nrow) * 128u
                             + (uint32_t)ks * 32u + (uint32_t)b_koff;
                ldsm_x4(bh[nt], s + 16384u + (off ^ ((off >> 3) & 0x70)));
            }
#pragma unroll
            for (int mt = 0; mt < 2; mt++)
#pragma unroll
                for (int n8 = 0; n8 < 8; n8++)
                    mma16816(acc[mt][n8], ah[mt], &bh[n8 >> 1][(n8 & 1) * 2]);
        }
        __syncthreads();   // compute done before this stage slot is reloaded
    }

    // epilogue -> bf16 sims
#pragma unroll
    for (int mt = 0; mt < 2; mt++) {
#pragma unroll
        for (int rg = 0; rg < 2; rg++) {
            int row = br + wm + mt * 16 + rg * 8 + (lane >> 2);
            __nv_bfloat162* dst = (__nv_bfloat162*)(g_simh + (size_t)row * KC + bc + wn)
                                  + (lane & 3);
#pragma unroll
            for (int n8 = 0; n8 < 8; n8++)
                dst[n8 * 4] = __float22bfloat162_rn(
                    make_float2(acc[mt][n8][rg * 2], acc[mt][n8][rg * 2 + 1]));
        }
    }
}

// 16 rows/CTA, 2 rows per iteration: softmax stats, entropy (log-free + eps
// correction), diversity, candidate collection (rescued in fp32 later)
#define RPC 16
__global__ __launch_bounds__(256)
void row_kernel() {
    __shared__ float divp[KC];
    __shared__ int scount[2];
    int t = threadIdx.x;
    for (int i = t; i < KC; i += 256) divp[i] = 0.0f;

    float ent_acc = 0.0f;     // accumulated on t==0 only
    int r0 = blockIdx.x * RPC;
    for (int rr = 0; rr < RPC; rr += 2) {
        int ra = r0 + rr, rb = ra + 1;
        if (t < 2) scount[t] = 0;
        __syncthreads();

        // each thread owns cols [t*8, t*8+8): one 16B bf16 load per row
        float4 qa = *(const float4*)(g_simh + (size_t)ra * KC + t * 8);
        float4 qb = *(const float4*)(g_simh + (size_t)rb * KC + t * 8);
        float va[8], vb[8];
        {
            const __nv_bfloat162* pa = (const __nv_bfloat162*)&qa;
            const __nv_bfloat162* pb = (const __nv_bfloat162*)&qb;
#pragma unroll
            for (int j = 0; j < 4; j++) {
                float2 fa = __bfloat1622float2(pa[j]);
                float2 fb = __bfloat1622float2(pb[j]);
                va[2 * j] = fa.x; va[2 * j + 1] = fa.y;
                vb[2 * j] = fb.x; vb[2 * j + 1] = fb.y;
            }
        }

        float ma = va[0], mb = vb[0];
#pragma unroll
        for (int j = 1; j < 8; j++) { ma = fmaxf(ma, va[j]); mb = fmaxf(mb, vb[j]); }
        float2 mm = blockMax2(ma, mb);

        float tha = mm.x - MARGIN, thb = mm.y - MARGIN;
#pragma unroll
        for (int j = 0; j < 8; j++) {
            if (va[j] > tha) {
                int p = atomicAdd(&scount[0], 1);
                if (p < MAXCAND) g_cand[ra][p] = t * 8 + j;
            }
            if (vb[j] > thb) {
                int p = atomicAdd(&scount[1], 1);
                if (p < MAXCAND) g_cand[rb][p] = t * 8 + j;
            }
        }

        float ea[8], eb[8];
        float za = 0.f, eva = 0.f, zb = 0.f, evb = 0.f;
#pragma unroll
        for (int j = 0; j < 8; j++) {
            ea[j] = __expf(va[j] - mm.x);
            eb[j] = __expf(vb[j] - mm.y);
            za += ea[j]; eva = fmaf(ea[j], va[j], eva);
            zb += eb[j]; evb = fmaf(eb[j], vb[j], evb);
        }
        float4 zz = blockSum4(za, eva, zb, evb);
        float ia = 1.0f / zz.x, ib = 1.0f / zz.z;
#pragma unroll
        for (int j = 0; j < 8; j++)
            divp[t * 8 + j] += ea[j] * ia + eb[j] * ib;

        if (t == 0) {
            ent_acc += 1.4426950408889634f * (zz.y * ia - mm.x) - log2f(zz.x) + EPS_CORR;
            ent_acc += 1.4426950408889634f * (zz.w * ib - mm.y) - log2f(zz.z) + EPS_CORR;
            g_ncand[ra] = scount[0];
            g_ncand[rb] = scount[1];
        }
    }
    if (t == 0) atomicAdd(&g_hsum, (double)ent_acc);
    __syncthreads();
    for (int i = t; i < KC; i += 256) atomicAdd(&g_div[i], divp[i]);
}

// exact fp32 rescue of argmax among candidates (one warp per row)
static __device__ __forceinline__ float dotrow(const float4 xv[4], const float* crow, int l) {
    const float4* c4 = (const float4*)crow;
    float s = 0.0f;
#pragma unroll
    for (int j = 0; j < 4; j++) {
        float4 c = c4[l + 32 * j];
        s = fmaf(xv[j].x, c.x, s);
        s = fmaf(xv[j].y, c.y, s);
        s = fmaf(xv[j].z, c.z, s);
        s = fmaf(xv[j].w, c.w, s);
    }
#pragma unroll
    for (int o = 16; o; o >>= 1) s += __shfl_xor_sync(0xffffffffu, s, o);
    return s;
}

__global__ __launch_bounds__(256)
void rescue_kernel(const float* __restrict__ x, const float* __restrict__ cb) {
    int w = (blockIdx.x * 256 + threadIdx.x) >> 5;   // row (grid exact)
    int l = threadIdx.x & 31;
    const float4* xr = (const float4*)(x + (size_t)w * DD);
    float4 xv[4];
#pragma unroll
    for (int j = 0; j < 4; j++) xv[j] = xr[l + 32 * j];

    int nc = g_ncand[w];
    float best = -3.4e38f;
    int bi = 0x7fffffff;
    if (nc <= MAXCAND) {
        for (int j = 0; j < nc; j++) {
            int col = g_cand[w][j];
            float d = dotrow(xv, cb + (size_t)col * DD, l);
            if (d > best || (d == best && col < bi)) { best = d; bi = col; }
        }
    } else {
        // overflow fallback: exact full scan (expected never)
        for (int col = 0; col < KC; col++) {
            float d = dotrow(xv, cb + (size_t)col * DD, l);
            if (d > best || (d == best && col < bi)) { best = d; bi = col; }
        }
    }
    if (l == 0) {
        g_idx[w] = bi;
        atomicAdd(&g_cnt[bi], 1.0f);
    }
}

// one warp per row: gather codebook row, center, L2-normalize, straight-through
__global__ __launch_bounds__(256)
void quant_kernel(const float* __restrict__ x, const float* __restrict__ cb,
                  float* __restrict__ oq, int nrows) {
    int w = (blockIdx.x * 256 + threadIdx.x) >> 5;
    if (w >= nrows) return;
    int l = threadIdx.x & 31;
    const float* crow = cb + (size_t)g_idx[w] * DD;
    const float* xrow = x + (size_t)w * DD;
    float4 q[4];
    float s = 0.0f;
#pragma unroll
    for (int j = 0; j < 4; j++) {
        q[j] = *(const float4*)(crow + j * 128 + l * 4);
        s += q[j].x + q[j].y + q[j].z + q[j].w;
    }
#pragma unroll
    for (int o = 16; o; o >>= 1) s += __shfl_xor_sync(0xffffffffu, s, o);
    float mean = s * (1.0f / (float)DD);
    float ss = 0.0f;
#pragma unroll
    for (int j = 0; j < 4; j++) {
        float dx = q[j].x - mean, dy = q[j].y - mean, dz = q[j].z - mean, dw = q[j].w - mean;
        ss += dx * dx + dy * dy + dz * dz + dw * dw;
    }
#pragma unroll
    for (int o = 16; o; o >>= 1) ss += __shfl_xor_sync(0xffffffffu, ss, o);
    float nrm = sqrtf(ss);
#pragma unroll
    for (int j = 0; j < 4; j++) {
        float4 xv = *(const float4*)(xrow + j * 128 + l * 4);
        float4 o4;
        o4.x = xv.x + ((q[j].x - mean) / nrm - xv.x);
        o4.y = xv.y + ((q[j].y - mean) / nrm - xv.y);
        o4.z = xv.z + ((q[j].z - mean) / nrm - xv.z);
        o4.w = xv.w + ((q[j].w - mean) / nrm - xv.w);
        *(float4*)(oq + (size_t)w * DD + j * 128 + l * 4) = o4;
    }
}

// fill o_loss with the scalar loss; each CTA recomputes it (cheap, avoids a
// separate single-block finalize launch)
__global__ __launch_bounds__(256)
void fill_loss_kernel(float4* __restrict__ o, size_t n4, float invN) {
    int t = threadIdx.x;
    float local = 0.0f;
    for (int i = t; i < KC; i += 256) {
        float d = g_div[i] * invN;
        local += d * log2f(d + EPSQ);
    }
    float HD = blockSum(local);                     // = -h_diversity
    float hclust = -(float)(g_hsum * (double)invN);
    float v = hclust + HD;                          // h_clust - h_diversity
    float4 f = make_float4(v, v, v, v);
    size_t i = (size_t)blockIdx.x * blockDim.x + threadIdx.x;
    size_t stride = (size_t)gridDim.x * blockDim.x;
    for (; i < n4; i += stride) o[i] = f;
}

__global__ void misc_kernel(const float* __restrict__ cb,
                            const float* __restrict__ old_counts,
                            const int* __restrict__ train,
                            float* __restrict__ o_idx,
                            float* __restrict__ o_cb,
                            float* __restrict__ o_cnt, int nrows) {
    int gid = blockIdx.x * blockDim.x + threadIdx.x;
    if (gid < (KC * DD) / 4) ((float4*)o_cb)[gid] = ((const float4*)cb)[gid];
    if (gid < nrows) o_idx[gid] = (float)g_idx[gid];
    if (gid < KC) {
        float oldc = old_counts[gid];
        o_cnt[gid] = (*train) ? (0.99f * oldc + 0.01f * g_cnt[gid]) : oldc;
    }
}

// ---------------- launch ----------------------------------------------------
extern "C" void kernel_launch(void* const* d_in, const int* in_sizes, int n_in,
                              void* d_out, int out_size) {
    const float* inputs   = (const float*)d_in[0];
    const float* codebook = (const float*)d_in[1];
    const float* counts   = (const float*)d_in[2];
    const int*   train    = (const int*)d_in[3];

    const int nrows = in_sizes[0] / DD;     // 16384

    float* out    = (float*)d_out;
    float* o_q    = out;
    float* o_loss = o_q + (size_t)nrows * DD;
    float* o_idx  = o_loss + (size_t)nrows * KC;
    float* o_cb   = o_idx + nrows;
    float* o_cnt  = o_cb + (size_t)KC * DD;

    const int MM_SMEM = 3 * 49152 + 1024;
    cudaFuncSetAttribute(mm_kernel, cudaFuncAttributeMaxDynamicSharedMemorySize, MM_SMEM);

    const int NA4 = NMAX * DD / 4, NB4 = KC * DD / 4;
    convert_kernel<<<(NA4 + NB4 + 255) / 256, 256>>>((const float4*)inputs,
                                                     (const float4*)codebook);

    dim3 gemm_grid(KC / BNN, nrows / BMM);
    mm_kernel<<<gemm_grid, 512, MM_SMEM>>>();

    row_kernel<<<nrows / RPC, 256>>>();

    rescue_kernel<<<nrows / 8, 256>>>(inputs, codebook);

    quant_kernel<<<(nrows + 7) / 8, 256>>>(inputs, codebook, o_q, nrows);

    size_t n4 = ((size_t)nrows * KC) / 4;
    fill_loss_kernel<<<592, 256>>>((float4*)o_loss, n4, 1.0f / (float)nrows);

    misc_kernel<<<(KC * DD / 4 + 255) / 256, 256>>>(codebook, counts, train,
                                                    o_idx, o_cb, o_cnt, nrows);
}

// round 17
// speedup vs baseline: 1.2525x; 1.2525x over previous
#include <cuda_runtime.h>
#include <cuda_bf16.h>
#include <math.h>
#include <stdint.h>

// Problem-instance constants (VectorQuantizerEnt: B=32,T=512,D=512,K=2048)
#define KC   2048
#define DD   512
#define NMAX 16384
#define EPSQ 1e-8f
#define MARGIN 0.02f
#define MAXCAND 16
// sum_k p*log2((p+eps)/p) ~= K*eps*log2(e)  (exact to ~3e-10 here since eps/p <= 1e-4)
#define EPS_CORR 2.9546194437325826e-5f

// ---------------- scratch (static device globals) ---------------------------
__device__ __nv_bfloat16 g_simh[(size_t)NMAX * KC];   // similarities, bf16 (67MB)
__device__ __nv_bfloat16 g_Ah[(size_t)NMAX * DD];
__device__ __nv_bfloat16 g_Bh[(size_t)KC * DD];
__device__ float  g_div[KC];
__device__ float  g_cnt[KC];
__device__ int    g_idx[NMAX];
__device__ int    g_cand[NMAX][MAXCAND];
__device__ int    g_ncand[NMAX];
__device__ double g_hsum;

// ---------------- small PTX helpers -----------------------------------------
static __device__ __forceinline__ uint32_t smem_u32(const void* p) {
    uint32_t a;
    asm("{ .reg .u64 t; cvta.to.shared.u64 t, %1; cvt.u32.u64 %0, t; }" : "=r"(a) : "l"(p));
    return a;
}
static __device__ __forceinline__ void ldsm_x4(uint32_t* r, uint32_t addr) {
    asm volatile("ldmatrix.sync.aligned.m8n8.x4.shared.b16 {%0,%1,%2,%3}, [%4];"
                 : "=r"(r[0]), "=r"(r[1]), "=r"(r[2]), "=r"(r[3]) : "r"(addr));
}
static __device__ __forceinline__ void mma16816(float* c, const uint32_t* a, const uint32_t* b) {
    asm volatile("mma.sync.aligned.m16n8k16.row.col.f32.bf16.bf16.f32 "
                 "{%0,%1,%2,%3}, {%4,%5,%6,%7}, {%8,%9}, {%0,%1,%2,%3};"
                 : "+f"(c[0]), "+f"(c[1]), "+f"(c[2]), "+f"(c[3])
                 : "r"(a[0]), "r"(a[1]), "r"(a[2]), "r"(a[3]), "r"(b[0]), "r"(b[1]));
}

// ---------------- reductions ------------------------------------------------
__device__ __forceinline__ float blockSum(float v) {
    __shared__ float s[8];
    int t = threadIdx.x, w = t >> 5, l = t & 31;
#pragma unroll
    for (int o = 16; o; o >>= 1) v += __shfl_xor_sync(0xffffffffu, v, o);
    if (l == 0) s[w] = v;
    __syncthreads();
    if (w == 0) {
        float x = (l < 8) ? s[l] : 0.0f;
#pragma unroll
        for (int o = 4; o; o >>= 1) x += __shfl_xor_sync(0xffffffffu, x, o);
        if (l == 0) s[0] = x;
    }
    __syncthreads();
    float r = s[0];
    __syncthreads();
    return r;
}

// block max of two values simultaneously
__device__ __forceinline__ float2 blockMax2(float a, float b) {
    __shared__ float2 s2[8];
    int t = threadIdx.x, w = t >> 5, l = t & 31;
#pragma unroll
    for (int o = 16; o; o >>= 1) {
        a = fmaxf(a, __shfl_xor_sync(0xffffffffu, a, o));
        b = fmaxf(b, __shfl_xor_sync(0xffffffffu, b, o));
    }
    if (l == 0) s2[w] = make_float2(a, b);
    __syncthreads();
    if (w == 0) {
        float x = (l < 8) ? s2[l].x : -3.4e38f;
        float y = (l < 8) ? s2[l].y : -3.4e38f;
#pragma unroll
        for (int o = 4; o; o >>= 1) {
            x = fmaxf(x, __shfl_xor_sync(0xffffffffu, x, o));
            y = fmaxf(y, __shfl_xor_sync(0xffffffffu, y, o));
        }
        if (l == 0) s2[0] = make_float2(x, y);
    }
    __syncthreads();
    float2 r = s2[0];
    __syncthreads();
    return r;
}

// block sum of four values simultaneously
__device__ __forceinline__ float4 blockSum4(float a, float b, float c, float d) {
    __shared__ float4 s4[8];
    int t = threadIdx.x, w = t >> 5, l = t & 31;
#pragma unroll
    for (int o = 16; o; o >>= 1) {
        a += __shfl_xor_sync(0xffffffffu, a, o);
        b += __shfl_xor_sync(0xffffffffu, b, o);
        c += __shfl_xor_sync(0xffffffffu, c, o);
        d += __shfl_xor_sync(0xffffffffu, d, o);
    }
    if (l == 0) s4[w] = make_float4(a, b, c, d);
    __syncthreads();
    if (w == 0) {
        float4 v = (l < 8) ? s4[l] : make_float4(0.f, 0.f, 0.f, 0.f);
#pragma unroll
        for (int o = 4; o; o >>= 1) {
            v.x += __shfl_xor_sync(0xffffffffu, v.x, o);
            v.y += __shfl_xor_sync(0xffffffffu, v.y, o);
            v.z += __shfl_xor_sync(0xffffffffu, v.z, o);
            v.w += __shfl_xor_sync(0xffffffffu, v.w, o);
        }
        if (l == 0) s4[0] = v;
    }
    __syncthreads();
    float4 r = s4[0];
    __syncthreads();
    return r;
}

// ---------------- kernels ---------------------------------------------------
// fp32 -> bf16 convert of inputs + codebook; also zero-init accumulators
__global__ void convert_kernel(const float4* __restrict__ A, const float4* __restrict__ B) {
    const int NA4 = NMAX * DD / 4;
    const int NB4 = KC * DD / 4;
    int i = blockIdx.x * 256 + threadIdx.x;
    if (i < KC) { g_div[i] = 0.0f; g_cnt[i] = 0.0f; }
    if (i == 0) g_hsum = 0.0;
    const float4* src;
    __nv_bfloat162* oh;
    int j;
    if (i < NA4) {
        src = A; j = i; oh = (__nv_bfloat162*)g_Ah;
    } else if (i < NA4 + NB4) {
        src = B; j = i - NA4; oh = (__nv_bfloat162*)g_Bh;
    } else return;
    float4 f = src[j];
    oh[2 * j]     = __floats2bfloat162_rn(f.x, f.y);
    oh[2 * j + 1] = __floats2bfloat162_rn(f.z, f.w);
}

// cp.async one 128x64 bf16 chunk (16KB) each for A and B into SW128 SMEM
// stage layout: [A:0, B:16K], stage size 32KB
static __device__ __forceinline__ void load_chunk(
    uint32_t s,
    const __nv_bfloat16* __restrict__ Ah, const __nv_bfloat16* __restrict__ Bh,
    int k0, int t)
{
    const char* pA = (const char*)(Ah + k0);
    const char* pB = (const char*)(Bh + k0);
#pragma unroll
    for (int i = 0; i < 4; i++) {
        int u = t + i * 256;           // 1024 16B units: 128 rows x 8 units
        int row = u >> 3, c16 = u & 7;
        uint32_t off = (uint32_t)row * 128u + (uint32_t)c16 * 16u;
        uint32_t sw  = off ^ ((off >> 3) & 0x70);
        size_t go = (size_t)row * (DD * 2) + c16 * 16;
        asm volatile("cp.async.cg.shared.global [%0], [%1], 16;" :: "r"(s + sw),          "l"(pA + go));
        asm volatile("cp.async.cg.shared.global [%0], [%1], 16;" :: "r"(s + 16384u + sw), "l"(pB + go));
    }
}

// C = A_bf16 * B_bf16^T via mma.sync m16n8k16 (fp32 accum).
// 128x128 tile, BK=64, double-buffered cp.async, 8 warps (4m x 2n), warp=32x64.
// 2 CTAs/SM (64KB smem each). Proven R12 config; epilogue stores bf16 sims.
__global__ __launch_bounds__(256, 2) void mm_kernel() {
    extern __shared__ char dyn[];
    uint32_t raw  = smem_u32(dyn);
    uint32_t base = (raw + 1023u) & ~1023u;
    int t = threadIdx.x, wid = t >> 5, lane = t & 31;
    int bc = blockIdx.x * 128, br = blockIdx.y * 128;
    int wm = (wid & 3) * 32;      // warp m offset in tile
    int wn = (wid >> 2) * 64;     // warp n offset in tile

    const __nv_bfloat16* Ah = g_Ah + (size_t)br * DD;
    const __nv_bfloat16* Bh = g_Bh + (size_t)bc * DD;

    float acc[2][8][4];
#pragma unroll
    for (int i = 0; i < 2; i++)
#pragma unroll
        for (int j = 0; j < 8; j++)
#pragma unroll
            for (int q = 0; q < 4; q++) acc[i][j][q] = 0.0f;

    // ldmatrix lane address components
    const int a_row  = lane & 15;               // + wm + mt*16
    const int a_koff = (lane >> 4) * 16;        // bytes (8 bf16)
    const int b_nrow = (lane & 7) + ((lane >> 4) * 8);  // + wn + nt*16
    const int b_koff = ((lane >> 3) & 1) * 16;  // bytes

    load_chunk(base, Ah, Bh, 0, t);
    asm volatile("cp.async.commit_group;");

    for (int c = 0; c < 8; c++) {
        uint32_t s = base + (uint32_t)(c & 1) * 32768u;
        if (c < 7) {
            uint32_t ns = base + (uint32_t)((c + 1) & 1) * 32768u;
            load_chunk(ns, Ah, Bh, (c + 1) * 64, t);
            asm volatile("cp.async.commit_group;");
            asm volatile("cp.async.wait_group 1;");
        } else {
            asm volatile("cp.async.wait_group 0;");
        }
        __syncthreads();

#pragma unroll
        for (int ks = 0; ks < 4; ks++) {
            uint32_t ah[2][4], bh[4][4];
#pragma unroll
            for (int mt = 0; mt < 2; mt++) {
                uint32_t off = (uint32_t)(wm + mt * 16 + a_row) * 128u
                             + (uint32_t)ks * 32u + (uint32_t)a_koff;
                ldsm_x4(ah[mt], s + (off ^ ((off >> 3) & 0x70)));
            }
#pragma unroll
            for (int nt = 0; nt < 4; nt++) {
                uint32_t off = (uint32_t)(wn + nt * 16 + b_nrow) * 128u
                             + (uint32_t)ks * 32u + (uint32_t)b_koff;
                ldsm_x4(bh[nt], s + 16384u + (off ^ ((off >> 3) & 0x70)));
            }
#pragma unroll
            for (int mt = 0; mt < 2; mt++)
#pragma unroll
                for (int n8 = 0; n8 < 8; n8++)
                    mma16816(acc[mt][n8], ah[mt], &bh[n8 >> 1][(n8 & 1) * 2]);
        }
        __syncthreads();   // protect buffer (c&1) before iter c+1 overwrites it
    }

    // epilogue -> bf16 sims (coalesced: 4 lanes x 4B contiguous per n8)
#pragma unroll
    for (int mt = 0; mt < 2; mt++) {
#pragma unroll
        for (int rg = 0; rg < 2; rg++) {
            int row = br + wm + mt * 16 + rg * 8 + (lane >> 2);
            __nv_bfloat162* dst = (__nv_bfloat162*)(g_simh + (size_t)row * KC + bc + wn)
                                  + (lane & 3);
#pragma unroll
            for (int n8 = 0; n8 < 8; n8++)
                dst[n8 * 4] = __float22bfloat162_rn(
                    make_float2(acc[mt][n8][rg * 2], acc[mt][n8][rg * 2 + 1]));
        }
    }
}

// 16 rows/CTA, 2 rows per iteration. Diversity accumulated in REGISTERS
// (each thread owns cols [t*8, t*8+8) for all rows), flushed once via atomics.
#define RPC 16
__global__ __launch_bounds__(256)
void row_kernel() {
    __shared__ int scount[2];
    int t = threadIdx.x;
    float divr[8];
#pragma unroll
    for (int j = 0; j < 8; j++) divr[j] = 0.0f;

    float ent_acc = 0.0f;     // accumulated on t==0 only
    int r0 = blockIdx.x * RPC;
    for (int rr = 0; rr < RPC; rr += 2) {
        int ra = r0 + rr, rb = ra + 1;
        if (t < 2) scount[t] = 0;
        __syncthreads();

        // one 16B bf16 load per row per thread
        float4 qa = *(const float4*)(g_simh + (size_t)ra * KC + t * 8);
        float4 qb = *(const float4*)(g_simh + (size_t)rb * KC + t * 8);
        float va[8], vb[8];
        {
            const __nv_bfloat162* pa = (const __nv_bfloat162*)&qa;
            const __nv_bfloat162* pb = (const __nv_bfloat162*)&qb;
#pragma unroll
            for (int j = 0; j < 4; j++) {
                float2 fa = __bfloat1622float2(pa[j]);
                float2 fb = __bfloat1622float2(pb[j]);
                va[2 * j] = fa.x; va[2 * j + 1] = fa.y;
                vb[2 * j] = fb.x; vb[2 * j + 1] = fb.y;
            }
        }

        float ma = va[0], mb = vb[0];
#pragma unroll
        for (int j = 1; j < 8; j++) { ma = fmaxf(ma, va[j]); mb = fmaxf(mb, vb[j]); }
        float2 mm = blockMax2(ma, mb);

        float tha = mm.x - MARGIN, thb = mm.y - MARGIN;
#pragma unroll
        for (int j = 0; j < 8; j++) {
            if (va[j] > tha) {
                int p = atomicAdd(&scount[0], 1);
                if (p < MAXCAND) g_cand[ra][p] = t * 8 + j;
            }
            if (vb[j] > thb) {
                int p = atomicAdd(&scount[1], 1);
                if (p < MAXCAND) g_cand[rb][p] = t * 8 + j;
            }
        }

        float ea[8], eb[8];
        float za = 0.f, eva = 0.f, zb = 0.f, evb = 0.f;
#pragma unroll
        for (int j = 0; j < 8; j++) {
            ea[j] = __expf(va[j] - mm.x);
            eb[j] = __expf(vb[j] - mm.y);
            za += ea[j]; eva = fmaf(ea[j], va[j], eva);
            zb += eb[j]; evb = fmaf(eb[j], vb[j], evb);
        }
        float4 zz = blockSum4(za, eva, zb, evb);
        float ia = 1.0f / zz.x, ib = 1.0f / zz.z;
#pragma unroll
        for (int j = 0; j < 8; j++)
            divr[j] += ea[j] * ia + eb[j] * ib;

        if (t == 0) {
            ent_acc += 1.4426950408889634f * (zz.y * ia - mm.x) - log2f(zz.x) + EPS_CORR;
            ent_acc += 1.4426950408889634f * (zz.w * ib - mm.y) - log2f(zz.z) + EPS_CORR;
            g_ncand[ra] = scount[0];
            g_ncand[rb] = scount[1];
        }
    }
    if (t == 0) atomicAdd(&g_hsum, (double)ent_acc);
#pragma unroll
    for (int j = 0; j < 8; j++) atomicAdd(&g_div[t * 8 + j], divr[j]);
}

// exact fp32 rescue of argmax among candidates (one warp per row)
static __device__ __forceinline__ float dotrow(const float4 xv[4], const float* crow, int l) {
    const float4* c4 = (const float4*)crow;
    float s = 0.0f;
#pragma unroll
    for (int j = 0; j < 4; j++) {
        float4 c = c4[l + 32 * j];
        s = fmaf(xv[j].x, c.x, s);
        s = fmaf(xv[j].y, c.y, s);
        s = fmaf(xv[j].z, c.z, s);
        s = fmaf(xv[j].w, c.w, s);
    }
#pragma unroll
    for (int o = 16; o; o >>= 1) s += __shfl_xor_sync(0xffffffffu, s, o);
    return s;
}

__global__ __launch_bounds__(256)
void rescue_kernel(const float* __restrict__ x, const float* __restrict__ cb) {
    int w = (blockIdx.x * 256 + threadIdx.x) >> 5;   // row (grid exact)
    int l = threadIdx.x & 31;
    const float4* xr = (const float4*)(x + (size_t)w * DD);
    float4 xv[4];
#pragma unroll
    for (int j = 0; j < 4; j++) xv[j] = xr[l + 32 * j];

    int nc = g_ncand[w];
    float best = -3.4e38f;
    int bi = 0x7fffffff;
    if (nc <= MAXCAND) {
        for (int j = 0; j < nc; j++) {
            int col = g_cand[w][j];
            float d = dotrow(xv, cb + (size_t)col * DD, l);
            if (d > best || (d == best && col < bi)) { best = d; bi = col; }
        }
    } else {
        // overflow fallback: exact full scan (expected never)
        for (int col = 0; col < KC; col++) {
            float d = dotrow(xv, cb + (size_t)col * DD, l);
            if (d > best || (d == best && col < bi)) { best = d; bi = col; }
        }
    }
    if (l == 0) {
        g_idx[w] = bi;
        atomicAdd(&g_cnt[bi], 1.0f);
    }
}

// one warp per row: gather codebook row, center, L2-normalize, straight-through
__global__ __launch_bounds__(256)
void quant_kernel(const float* __restrict__ x, const float* __restrict__ cb,
                  float* __restrict__ oq, int nrows) {
    int w = (blockIdx.x * 256 + threadIdx.x) >> 5;
    if (w >= nrows) return;
    int l = threadIdx.x & 31;
    const float* crow = cb + (size_t)g_idx[w] * DD;
    const float* xrow = x + (size_t)w * DD;
    float4 q[4];
    float s = 0.0f;
#pragma unroll
    for (int j = 0; j < 4; j++) {
        q[j] = *(const float4*)(crow + j * 128 + l * 4);
        s += q[j].x + q[j].y + q[j].z + q[j].w;
    }
#pragma unroll
    for (int o = 16; o; o >>= 1) s += __shfl_xor_sync(0xffffffffu, s, o);
    float mean = s * (1.0f / (float)DD);
    float ss = 0.0f;
#pragma unroll
    for (int j = 0; j < 4; j++) {
        float dx = q[j].x - mean, dy = q[j].y - mean, dz = q[j].z - mean, dw = q[j].w - mean;
        ss += dx * dx + dy * dy + dz * dz + dw * dw;
    }
#pragma unroll
    for (int o = 16; o; o >>= 1) ss += __shfl_xor_sync(0xffffffffu, ss, o);
    float nrm = sqrtf(ss);
#pragma unroll
    for (int j = 0; j < 4; j++) {
        float4 xv = *(const float4*)(xrow + j * 128 + l * 4);
        float4 o4;
        o4.x = xv.x + ((q[j].x - mean) / nrm - xv.x);
        o4.y = xv.y + ((q[j].y - mean) / nrm - xv.y);
        o4.z = xv.z + ((q[j].z - mean) / nrm - xv.z);
        o4.w = xv.w + ((q[j].w - mean) / nrm - xv.w);
        *(float4*)(oq + (size_t)w * DD + j * 128 + l * 4) = o4;
    }
}

// fill o_loss with the scalar loss; each CTA recomputes it (cheap, avoids a
// separate single-block finalize launch)
__global__ __launch_bounds__(256)
void fill_loss_kernel(float4* __restrict__ o, size_t n4, float invN) {
    int t = threadIdx.x;
    float local = 0.0f;
    for (int i = t; i < KC; i += 256) {
        float d = g_div[i] * invN;
        local += d * log2f(d + EPSQ);
    }
    float HD = blockSum(local);                     // = -h_diversity
    float hclust = -(float)(g_hsum * (double)invN);
    float v = hclust + HD;                          // h_clust - h_diversity
    float4 f = make_float4(v, v, v, v);
    size_t i = (size_t)blockIdx.x * blockDim.x + threadIdx.x;
    size_t stride = (size_t)gridDim.x * blockDim.x;
    for (; i < n4; i += stride) o[i] = f;
}

__global__ void misc_kernel(const float* __restrict__ cb,
                            const float* __restrict__ old_counts,
                            const int* __restrict__ train,
                            float* __restrict__ o_idx,
                            float* __restrict__ o_cb,
                            float* __restrict__ o_cnt, int nrows) {
    int gid = blockIdx.x * blockDim.x + threadIdx.x;
    if (gid < (KC * DD) / 4) ((float4*)o_cb)[gid] = ((const float4*)cb)[gid];
    if (gid < nrows) o_idx[gid] = (float)g_idx[gid];
    if (gid < KC) {
        float oldc = old_counts[gid];
        o_cnt[gid] = (*train) ? (0.99f * oldc + 0.01f * g_cnt[gid]) : oldc;
    }
}

// ---------------- launch ----------------------------------------------------
extern "C" void kernel_launch(void* const* d_in, const int* in_sizes, int n_in,
                              void* d_out, int out_size) {
    const float* inputs   = (const float*)d_in[0];
    const float* codebook = (const float*)d_in[1];
    const float* counts   = (const float*)d_in[2];
    const int*   train    = (const int*)d_in[3];

    const int nrows = in_sizes[0] / DD;     // 16384

    float* out    = (float*)d_out;
    float* o_q    = out;
    float* o_loss = o_q + (size_t)nrows * DD;
    float* o_idx  = o_loss + (size_t)nrows * KC;
    float* o_cb   = o_idx + nrows;
    float* o_cnt  = o_cb + (size_t)KC * DD;

    const int MM_SMEM = 65536 + 1024;
    cudaFuncSetAttribute(mm_kernel, cudaFuncAttributeMaxDynamicSharedMemorySize, MM_SMEM);

    const int NA4 = NMAX * DD / 4, NB4 = KC * DD / 4;
    convert_kernel<<<(NA4 + NB4 + 255) / 256, 256>>>((const float4*)inputs,
                                                     (const float4*)codebook);

    dim3 gemm_grid(KC / 128, nrows / 128);
    mm_kernel<<<gemm_grid, 256, MM_SMEM>>>();

    row_kernel<<<nrows / RPC, 256>>>();

    rescue_kernel<<<nrows / 8, 256>>>(inputs, codebook);

    quant_kernel<<<(nrows + 7) / 8, 256>>>(inputs, codebook, o_q, nrows);

    size_t n4 = ((size_t)nrows * KC) / 4;
    fill_loss_kernel<<<2368, 256>>>((float4*)o_loss, n4, 1.0f / (float)nrows);

    misc_kernel<<<(KC * DD / 4 + 255) / 256, 256>>>(codebook, counts, train,
                                                    o_idx, o_cb, o_cnt, nrows);
}